// round 1
// baseline (speedup 1.0000x reference)
#include <cuda_runtime.h>

// Problem constants
#define NTOK 2048      // B*S
#define DIN  768       // D
#define NEXP 8         // E
#define DOUT 3072      // O
#define NO   (NTOK*DOUT)

// GEMM tiling
#define BM 64
#define BN 64
#define BK 16
#define SPAD 68        // padded shared stride (keeps float4 alignment, de-conflicts)

// ---------------- scratch (device globals: no allocations allowed) ----------
__device__ int   g_counts[NEXP];
__device__ float g_importance[NEXP];
__device__ int   g_list[NEXP * NTOK];
__device__ float g_gateval[NEXP * NTOK];

// ---------------- kernel 0: zero counters ----------------------------------
__global__ void zero_kernel() {
    int t = threadIdx.x;
    if (t < NEXP) { g_counts[t] = 0; g_importance[t] = 0.0f; }
}

// ---------------- kernel 1: gating (one block per token) --------------------
__global__ __launch_bounds__(128)
void gate_kernel(const float* __restrict__ x, const float* __restrict__ wg) {
    int n = blockIdx.x;
    int tid = threadIdx.x;

    float acc[NEXP];
#pragma unroll
    for (int e = 0; e < NEXP; e++) acc[e] = 0.0f;

    const float* xr = x + (size_t)n * DIN;
    for (int d = tid; d < DIN; d += 128) {
        float xv = xr[d];
#pragma unroll
        for (int e = 0; e < NEXP; e++) acc[e] += xv * wg[d * NEXP + e];
    }

    __shared__ float s[128][NEXP];
#pragma unroll
    for (int e = 0; e < NEXP; e++) s[tid][e] = acc[e];
    __syncthreads();
    for (int off = 64; off > 0; off >>= 1) {
        if (tid < off) {
#pragma unroll
            for (int e = 0; e < NEXP; e++) s[tid][e] += s[tid + off][e];
        }
        __syncthreads();
    }

    if (tid == 0) {
        float v[NEXP];
#pragma unroll
        for (int e = 0; e < NEXP; e++) v[e] = s[0][e];

        // top-2 with strict > : earliest index wins ties (matches jax top_k)
        float best = v[0], second = -3.4e38f;
        int bi = 0, si = -1;
#pragma unroll
        for (int e = 1; e < NEXP; e++) {
            if (v[e] > best)        { second = best; si = bi; best = v[e]; bi = e; }
            else if (v[e] > second) { second = v[e]; si = e; }
        }

        // softmax over the two top logits
        float e1 = __expf(second - best);
        float inv = 1.0f / (1.0f + e1);
        float g0 = inv;
        float g1 = e1 * inv;

        atomicAdd(&g_importance[bi], g0);
        atomicAdd(&g_importance[si], g1);

        int p0 = atomicAdd(&g_counts[bi], 1);
        g_list[bi * NTOK + p0]   = n;
        g_gateval[bi * NTOK + p0] = g0;
        int p1 = atomicAdd(&g_counts[si], 1);
        g_list[si * NTOK + p1]   = n;
        g_gateval[si * NTOK + p1] = g1;
    }
}

// ---------------- kernel 2: load-balance loss -------------------------------
__global__ void loss_kernel(float* __restrict__ out, int out_size) {
    if (out_size <= NO) return;
    float mi = 0.0f, ml = 0.0f;
#pragma unroll
    for (int e = 0; e < NEXP; e++) { mi += g_importance[e]; ml += (float)g_counts[e]; }
    mi *= (1.0f / NEXP); ml *= (1.0f / NEXP);
    float vi = 0.0f, vl = 0.0f;
#pragma unroll
    for (int e = 0; e < NEXP; e++) {
        float di = g_importance[e] - mi;        vi += di * di;
        float dl = (float)g_counts[e] - ml;     vl += dl * dl;
    }
    vi *= (1.0f / (NEXP - 1)); vl *= (1.0f / (NEXP - 1));
    float loss = 0.01f * (vi / (mi * mi + 1e-10f) + vl / (ml * ml + 1e-10f));
    out[NO] = loss;
}

// ---------------- kernel 3: static GEMM  y = x @ static_w^T ----------------
// x: [NTOK, DIN] row-major, w: [DOUT, DIN] row-major (NT gemm, K contiguous)
__global__ __launch_bounds__(256)
void static_gemm(const float* __restrict__ x, const float* __restrict__ w,
                 float* __restrict__ y) {
    __shared__ float xs[BK][SPAD];
    __shared__ float ws[BK][SPAD];

    int tid = threadIdx.x;
    int tx = tid & 15, ty = tid >> 4;
    int n0 = blockIdx.x * BN;
    int m0 = blockIdx.y * BM;

    int lrow = tid >> 2;          // 0..63
    int lk   = (tid & 3) * 4;     // 0,4,8,12

    const float* xg = x + (size_t)(m0 + lrow) * DIN + lk;
    const float* wg = w + (size_t)(n0 + lrow) * DIN + lk;

    float acc[4][4] = {};

    for (int kt = 0; kt < DIN; kt += BK) {
        float4 xa = *(const float4*)(xg + kt);
        float4 wa = *(const float4*)(wg + kt);
        xs[lk + 0][lrow] = xa.x; xs[lk + 1][lrow] = xa.y;
        xs[lk + 2][lrow] = xa.z; xs[lk + 3][lrow] = xa.w;
        ws[lk + 0][lrow] = wa.x; ws[lk + 1][lrow] = wa.y;
        ws[lk + 2][lrow] = wa.z; ws[lk + 3][lrow] = wa.w;
        __syncthreads();

#pragma unroll
        for (int k = 0; k < BK; k++) {
            float4 a4 = *(const float4*)&xs[k][ty * 4];
            float4 b4 = *(const float4*)&ws[k][tx * 4];
            float av[4] = {a4.x, a4.y, a4.z, a4.w};
            float bv[4] = {b4.x, b4.y, b4.z, b4.w};
#pragma unroll
            for (int i = 0; i < 4; i++)
#pragma unroll
                for (int j = 0; j < 4; j++)
                    acc[i][j] += av[i] * bv[j];
        }
        __syncthreads();
    }

#pragma unroll
    for (int i = 0; i < 4; i++) {
        float4 st = {acc[i][0], acc[i][1], acc[i][2], acc[i][3]};
        *(float4*)(y + (size_t)(m0 + ty * 4 + i) * DOUT + n0 + tx * 4) = st;
    }
}

// ---------------- kernel 4: per-expert gathered GEMM ------------------------
// For expert e, tokens g_list[e][0..cnt): y[tok] += g * (x[tok] @ W_e^T + b_e)
__global__ __launch_bounds__(256)
void expert_gemm(const float* __restrict__ x, const float* __restrict__ ew,
                 const float* __restrict__ eb, float* __restrict__ y) {
    int e = blockIdx.z;
    int cnt = g_counts[e];
    int m0 = blockIdx.y * BM;
    if (m0 >= cnt) return;
    int n0 = blockIdx.x * BN;

    __shared__ float xs[BK][SPAD];
    __shared__ float ws[BK][SPAD];
    __shared__ int   tok_s[BM];
    __shared__ float gat_s[BM];

    int tid = threadIdx.x;
    int tx = tid & 15, ty = tid >> 4;
    int lrow = tid >> 2;
    int lk   = (tid & 3) * 4;

    if (tid < BM) {
        int idx = m0 + tid;
        if (idx < cnt) {
            tok_s[tid] = g_list[e * NTOK + idx];
            gat_s[tid] = g_gateval[e * NTOK + idx];
        } else {
            tok_s[tid] = -1;
            gat_s[tid] = 0.0f;
        }
    }
    __syncthreads();

    int mytok = tok_s[lrow];
    const float* wr = ew + ((size_t)e * DOUT + n0 + lrow) * DIN + lk;
    const float* xr = (mytok >= 0) ? (x + (size_t)mytok * DIN + lk) : x;

    float acc[4][4] = {};

    for (int kt = 0; kt < DIN; kt += BK) {
        float4 xa;
        if (mytok >= 0) xa = *(const float4*)(xr + kt);
        else            xa = make_float4(0.f, 0.f, 0.f, 0.f);
        float4 wa = *(const float4*)(wr + kt);

        xs[lk + 0][lrow] = xa.x; xs[lk + 1][lrow] = xa.y;
        xs[lk + 2][lrow] = xa.z; xs[lk + 3][lrow] = xa.w;
        ws[lk + 0][lrow] = wa.x; ws[lk + 1][lrow] = wa.y;
        ws[lk + 2][lrow] = wa.z; ws[lk + 3][lrow] = wa.w;
        __syncthreads();

#pragma unroll
        for (int k = 0; k < BK; k++) {
            float4 a4 = *(const float4*)&xs[k][ty * 4];
            float4 b4 = *(const float4*)&ws[k][tx * 4];
            float av[4] = {a4.x, a4.y, a4.z, a4.w};
            float bv[4] = {b4.x, b4.y, b4.z, b4.w};
#pragma unroll
            for (int i = 0; i < 4; i++)
#pragma unroll
                for (int j = 0; j < 4; j++)
                    acc[i][j] += av[i] * bv[j];
        }
        __syncthreads();
    }

    const float* bp = eb + (size_t)e * DOUT + n0 + tx * 4;
#pragma unroll
    for (int i = 0; i < 4; i++) {
        int r = ty * 4 + i;
        int tok = tok_s[r];
        if (tok < 0) continue;
        float g = gat_s[r];
        float* yp = y + (size_t)tok * DOUT + n0 + tx * 4;
#pragma unroll
        for (int j = 0; j < 4; j++)
            atomicAdd(yp + j, g * (acc[i][j] + bp[j]));
    }
}

// ---------------- launch ----------------------------------------------------
extern "C" void kernel_launch(void* const* d_in, const int* in_sizes, int n_in,
                              void* d_out, int out_size) {
    const float* x        = (const float*)d_in[0];   // [B,S,D] = [2048,768]
    const float* w_gate   = (const float*)d_in[1];   // [D,E]
    const float* expert_w = (const float*)d_in[2];   // [E,O,D]
    const float* expert_b = (const float*)d_in[3];   // [E,O]
    const float* static_w = (const float*)d_in[4];   // [O,D]
    float* out = (float*)d_out;

    zero_kernel<<<1, 32>>>();
    gate_kernel<<<NTOK, 128>>>(x, w_gate);
    loss_kernel<<<1, 1>>>(out, out_size);

    dim3 sgrid(DOUT / BN, NTOK / BM);                // 48 x 32
    static_gemm<<<sgrid, 256>>>(x, static_w, out);

    dim3 egrid(DOUT / BN, NTOK / BM, NEXP);          // 48 x 32 x 8 (early-exit)
    expert_gemm<<<egrid, 256>>>(x, expert_w, expert_b, out);
}

// round 3
// speedup vs baseline: 2.4057x; 2.4057x over previous
#include <cuda_runtime.h>
#include <cuda_bf16.h>
#include <cstdint>

// ---------------- problem constants ----------------
#define NTOK 2048      // B*S
#define DIN  768       // D
#define NEXP 8         // E
#define DOUT 3072      // O
#define NO   (NTOK*DOUT)

// ---------------- GEMM tiling ----------------
#define BM 128
#define BN 128
#define BK 32                  // bf16 elems per chunk (64B per row)
#define NCH (DIN/BK)           // 24
#define RSTRIDE 80             // smem row stride in bytes (conflict-free ldmatrix)

// smem layout
#define OFF_TOK 0              // 128 int
#define OFF_GAT 512            // 128 float
#define OFF_EBS 1024           // 128 float
#define OFF_ST0 2048
#define AHI 0
#define ALO (128*RSTRIDE)      // 10240
#define BHI (2*128*RSTRIDE)    // 20480
#define BLO (3*128*RSTRIDE)    // 30720
#define STAGE_SZ (4*128*RSTRIDE)   // 40960
#define SMEM_SZ (OFF_ST0 + 2*STAGE_SZ)  // 83968

// ---------------- device scratch ----------------
__device__ int   g_counts[NEXP];
__device__ float g_importance[NEXP];
__device__ int   g_list[NEXP * NTOK];
__device__ float g_gateval[NEXP * NTOK];

__device__ __align__(256) __nv_bfloat16 g_xhi[NTOK*DIN];
__device__ __align__(256) __nv_bfloat16 g_xlo[NTOK*DIN];
__device__ __align__(256) __nv_bfloat16 g_swhi[DOUT*DIN];
__device__ __align__(256) __nv_bfloat16 g_swlo[DOUT*DIN];
__device__ __align__(256) __nv_bfloat16 g_ewhi[NEXP*DOUT*DIN];
__device__ __align__(256) __nv_bfloat16 g_ewlo[NEXP*DOUT*DIN];

// ---------------- PTX helpers (all baseline sm_80+, no 'a' features) -------
__device__ __forceinline__ uint32_t smem_u32(const void* p) {
    uint32_t a;
    asm("{ .reg .u64 t; cvta.to.shared.u64 t, %1; cvt.u32.u64 %0, t; }"
        : "=r"(a) : "l"(p));
    return a;
}
__device__ __forceinline__ void cpasync16(uint32_t dst, const void* src) {
    asm volatile("cp.async.cg.shared.global [%0], [%1], 16;" :: "r"(dst), "l"(src));
}
#define CP_COMMIT() asm volatile("cp.async.commit_group;" ::: "memory")
#define CP_WAIT(n)  asm volatile("cp.async.wait_group %0;" :: "n"(n) : "memory")

__device__ __forceinline__ void ldsm4(uint32_t* r, uint32_t addr) {
    asm volatile("ldmatrix.sync.aligned.m8n8.x4.shared.b16 {%0,%1,%2,%3}, [%4];"
        : "=r"(r[0]), "=r"(r[1]), "=r"(r[2]), "=r"(r[3]) : "r"(addr));
}
__device__ __forceinline__ void mma16816(float* c, const uint32_t* a,
                                         uint32_t b0, uint32_t b1) {
    asm volatile("mma.sync.aligned.m16n8k16.row.col.f32.bf16.bf16.f32 "
        "{%0,%1,%2,%3}, {%4,%5,%6,%7}, {%8,%9}, {%0,%1,%2,%3};"
        : "+f"(c[0]), "+f"(c[1]), "+f"(c[2]), "+f"(c[3])
        : "r"(a[0]), "r"(a[1]), "r"(a[2]), "r"(a[3]), "r"(b0), "r"(b1));
}

// ---------------- kernel: zero counters ----------------
__global__ void zero_kernel() {
    int t = threadIdx.x;
    if (t < NEXP) { g_counts[t] = 0; g_importance[t] = 0.0f; }
}

// ---------------- kernel: gating (one block per token) ----------------
__global__ __launch_bounds__(128)
void gate_kernel(const float* __restrict__ x, const float* __restrict__ wg) {
    int n = blockIdx.x;
    int tid = threadIdx.x;
    float acc[NEXP];
#pragma unroll
    for (int e = 0; e < NEXP; e++) acc[e] = 0.0f;
    const float* xr = x + (size_t)n * DIN;
    for (int d = tid; d < DIN; d += 128) {
        float xv = xr[d];
#pragma unroll
        for (int e = 0; e < NEXP; e++) acc[e] += xv * wg[d * NEXP + e];
    }
    __shared__ float s[128][NEXP];
#pragma unroll
    for (int e = 0; e < NEXP; e++) s[tid][e] = acc[e];
    __syncthreads();
    for (int off = 64; off > 0; off >>= 1) {
        if (tid < off) {
#pragma unroll
            for (int e = 0; e < NEXP; e++) s[tid][e] += s[tid + off][e];
        }
        __syncthreads();
    }
    if (tid == 0) {
        float v[NEXP];
#pragma unroll
        for (int e = 0; e < NEXP; e++) v[e] = s[0][e];
        float best = v[0], second = -3.4e38f;
        int bi = 0, si = -1;
#pragma unroll
        for (int e = 1; e < NEXP; e++) {
            if (v[e] > best)        { second = best; si = bi; best = v[e]; bi = e; }
            else if (v[e] > second) { second = v[e]; si = e; }
        }
        float e1 = __expf(second - best);
        float inv = 1.0f / (1.0f + e1);
        float g0 = inv, g1 = e1 * inv;
        atomicAdd(&g_importance[bi], g0);
        atomicAdd(&g_importance[si], g1);
        int p0 = atomicAdd(&g_counts[bi], 1);
        g_list[bi * NTOK + p0] = n;  g_gateval[bi * NTOK + p0] = g0;
        int p1 = atomicAdd(&g_counts[si], 1);
        g_list[si * NTOK + p1] = n;  g_gateval[si * NTOK + p1] = g1;
    }
}

// ---------------- kernel: loss ----------------
__global__ void loss_kernel(float* __restrict__ out, int out_size) {
    if (out_size <= NO) return;
    float mi = 0.0f, ml = 0.0f;
#pragma unroll
    for (int e = 0; e < NEXP; e++) { mi += g_importance[e]; ml += (float)g_counts[e]; }
    mi *= (1.0f / NEXP); ml *= (1.0f / NEXP);
    float vi = 0.0f, vl = 0.0f;
#pragma unroll
    for (int e = 0; e < NEXP; e++) {
        float di = g_importance[e] - mi;    vi += di * di;
        float dl = (float)g_counts[e] - ml; vl += dl * dl;
    }
    vi *= (1.0f / (NEXP - 1)); vl *= (1.0f / (NEXP - 1));
    out[NO] = 0.01f * (vi / (mi * mi + 1e-10f) + vl / (ml * ml + 1e-10f));
}

// ---------------- kernel: fp32 -> bf16 hi/lo split ----------------
__global__ __launch_bounds__(256)
void split_kernel(const float* __restrict__ s, int sel, int n4) {
    int i = blockIdx.x * 256 + threadIdx.x;
    if (i >= n4) return;
    __nv_bfloat16 *hp, *lp;
    if (sel == 0)      { hp = g_xhi;  lp = g_xlo;  }
    else if (sel == 1) { hp = g_swhi; lp = g_swlo; }
    else               { hp = g_ewhi; lp = g_ewlo; }
    float4 v = ((const float4*)s)[i];
    float a[4] = {v.x, v.y, v.z, v.w};
    unsigned short hh[4], ll[4];
#pragma unroll
    for (int k = 0; k < 4; k++) {
        __nv_bfloat16 h = __float2bfloat16(a[k]);
        __nv_bfloat16 l = __float2bfloat16(a[k] - __bfloat162float(h));
        hh[k] = __bfloat16_as_ushort(h);
        ll[k] = __bfloat16_as_ushort(l);
    }
    ((ushort4*)hp)[i] = make_ushort4(hh[0], hh[1], hh[2], hh[3]);
    ((ushort4*)lp)[i] = make_ushort4(ll[0], ll[1], ll[2], ll[3]);
}

// ---------------- kernel: bf16x3 mma.sync GEMM ----------------
// EXPERT=false: y[m0+r] = x[m0+r] . static_w^T            (plain stores)
// EXPERT=true : y[tok]  += g * (x[tok] . W_e^T + b_e)     (atomicAdd)
template<bool EXPERT>
__global__ __launch_bounds__(256, 1)
void moe_gemm_mma(float* __restrict__ y, const float* __restrict__ eb) {
    extern __shared__ char sm[];
    uint32_t sb = smem_u32(sm);
    int tid = threadIdx.x, wid = tid >> 5, lane = tid & 31;
    int n0 = blockIdx.x * BN;
    int m0 = blockIdx.y * BM;
    int e  = EXPERT ? blockIdx.z : 0;
    int cnt = EXPERT ? g_counts[e] : NTOK;
    if (EXPERT && m0 >= cnt) return;

    int* tok_s   = (int*)(sm + OFF_TOK);
    float* gat_s = (float*)(sm + OFF_GAT);
    float* ebs   = (float*)(sm + OFF_EBS);
    if (EXPERT) {
        if (tid < BM) {
            int idx = m0 + tid;
            if (idx < cnt) { tok_s[tid] = g_list[e*NTOK + idx]; gat_s[tid] = g_gateval[e*NTOK + idx]; }
            else           { tok_s[tid] = -1; gat_s[tid] = 0.0f; }
        }
        if (tid < BN) ebs[tid] = eb[(size_t)e*DOUT + n0 + tid];
        __syncthreads();
    }

    // ---- cp.async source/dest geometry: 8 x 16B per thread per stage ----
    int c  = tid & 3;                 // 16B chunk in row
    int rr = tid >> 2;                // 0..63
    size_t srcA[2]; size_t srcB[2]; uint32_t dstA[2], dstB[2];
    size_t wbase = EXPERT ? (size_t)e * DOUT * DIN : 0;
#pragma unroll
    for (int i = 0; i < 2; i++) {
        int r = rr + i * 64;
        int arow;
        if (EXPERT) { int t = tok_s[r]; arow = (t < 0) ? 0 : t; }
        else        arow = m0 + r;
        srcA[i] = (size_t)arow * DIN + c * 8;
        srcB[i] = wbase + (size_t)(n0 + r) * DIN + c * 8;
        dstA[i] = r * RSTRIDE + c * 16;
        dstB[i] = r * RSTRIDE + c * 16;
    }
    const __nv_bfloat16* WH = EXPERT ? g_ewhi : g_swhi;
    const __nv_bfloat16* WL = EXPERT ? g_ewlo : g_swlo;

    auto load_chunk = [&](int ch, uint32_t stg) {
        int off = ch * BK;
        uint32_t s0 = sb + OFF_ST0 + stg;
#pragma unroll
        for (int i = 0; i < 2; i++) {
            cpasync16(s0 + AHI + dstA[i], g_xhi + srcA[i] + off);
            cpasync16(s0 + ALO + dstA[i], g_xlo + srcA[i] + off);
            cpasync16(s0 + BHI + dstB[i], WH + srcB[i] + off);
            cpasync16(s0 + BLO + dstB[i], WL + srcB[i] + off);
        }
        CP_COMMIT();
    };

    // ---- ldmatrix per-lane base offsets ----
    int wm = (wid >> 2) * 64;         // warp m origin (2 warps)
    int wn = (wid & 3) * 32;          // warp n origin (4 warps)
    int mat = lane >> 3, r8 = lane & 7;
    // A: matrices (m0-7,k0)(m8-15,k0)(m0-7,k8)(m8-15,k8)
    uint32_t aoff = (uint32_t)((wm + (mat & 1) * 8 + r8) * RSTRIDE + (mat >> 1) * 16);
    // B: matrices (n0-7,k0)(n0-7,k8)(n8-15,k0)(n8-15,k8)
    uint32_t boff = (uint32_t)((wn + ((mat >> 1) & 1) * 8 + r8) * RSTRIDE + (mat & 1) * 16);

    float acc[4][4][4] = {};

    load_chunk(0, 0);
    for (int ch = 0; ch < NCH; ch++) {
        uint32_t stg = (uint32_t)(ch & 1) * STAGE_SZ;
        if (ch + 1 < NCH) {
            load_chunk(ch + 1, (uint32_t)((ch + 1) & 1) * STAGE_SZ);
            CP_WAIT(1);
        } else {
            CP_WAIT(0);
        }
        __syncthreads();

        uint32_t aHi = sb + OFF_ST0 + stg + AHI + aoff;
        uint32_t aLo = sb + OFF_ST0 + stg + ALO + aoff;
        uint32_t bHi = sb + OFF_ST0 + stg + BHI + boff;
        uint32_t bLo = sb + OFF_ST0 + stg + BLO + boff;

#pragma unroll
        for (int ks = 0; ks < 2; ks++) {
            uint32_t ah[4][4], al[4][4], bh[2][4], bl[2][4];
#pragma unroll
            for (int mi = 0; mi < 4; mi++) {
                ldsm4(ah[mi], aHi + mi * (16 * RSTRIDE) + ks * 32);
                ldsm4(al[mi], aLo + mi * (16 * RSTRIDE) + ks * 32);
            }
#pragma unroll
            for (int nt = 0; nt < 2; nt++) {
                ldsm4(bh[nt], bHi + nt * (16 * RSTRIDE) + ks * 32);
                ldsm4(bl[nt], bLo + nt * (16 * RSTRIDE) + ks * 32);
            }
#pragma unroll
            for (int mi = 0; mi < 4; mi++) {
#pragma unroll
                for (int nj = 0; nj < 4; nj++) {
                    uint32_t h0 = bh[nj >> 1][(nj & 1) * 2];
                    uint32_t h1 = bh[nj >> 1][(nj & 1) * 2 + 1];
                    uint32_t l0 = bl[nj >> 1][(nj & 1) * 2];
                    uint32_t l1 = bl[nj >> 1][(nj & 1) * 2 + 1];
                    mma16816(acc[mi][nj], ah[mi], h0, h1);   // hi*hi
                    mma16816(acc[mi][nj], ah[mi], l0, l1);   // hi*lo
                    mma16816(acc[mi][nj], al[mi], h0, h1);   // lo*hi
                }
            }
        }
        __syncthreads();
    }

    // ---- epilogue ----
    int t4r = lane >> 2;                  // 0..7
    int t4c = (lane & 3) * 2;             // 0,2,4,6
#pragma unroll
    for (int mi = 0; mi < 4; mi++) {
#pragma unroll
        for (int half = 0; half < 2; half++) {
            int r = wm + mi * 16 + half * 8 + t4r;          // tile row 0..127
            if (!EXPERT) {
                float* yr = y + (size_t)(m0 + r) * DOUT + n0;
#pragma unroll
                for (int nj = 0; nj < 4; nj++) {
                    int cn = wn + nj * 8 + t4c;
                    float2 v = { acc[mi][nj][half*2], acc[mi][nj][half*2+1] };
                    *(float2*)(yr + cn) = v;
                }
            } else {
                int tok = tok_s[r];
                if (tok < 0) continue;
                float g = gat_s[r];
                float* yr = y + (size_t)tok * DOUT + n0;
#pragma unroll
                for (int nj = 0; nj < 4; nj++) {
                    int cn = wn + nj * 8 + t4c;
                    atomicAdd(yr + cn,     g * (acc[mi][nj][half*2]   + ebs[cn]));
                    atomicAdd(yr + cn + 1, g * (acc[mi][nj][half*2+1] + ebs[cn+1]));
                }
            }
        }
    }
}

// ---------------- launch ----------------
extern "C" void kernel_launch(void* const* d_in, const int* in_sizes, int n_in,
                              void* d_out, int out_size) {
    const float* x        = (const float*)d_in[0];   // [2048, 768]
    const float* w_gate   = (const float*)d_in[1];   // [768, 8]
    const float* expert_w = (const float*)d_in[2];   // [8, 3072, 768]
    const float* expert_b = (const float*)d_in[3];   // [8, 3072]
    const float* static_w = (const float*)d_in[4];   // [3072, 768]
    float* out = (float*)d_out;

    cudaFuncSetAttribute(moe_gemm_mma<false>, cudaFuncAttributeMaxDynamicSharedMemorySize, SMEM_SZ);
    cudaFuncSetAttribute(moe_gemm_mma<true>,  cudaFuncAttributeMaxDynamicSharedMemorySize, SMEM_SZ);

    zero_kernel<<<1, 32>>>();
    gate_kernel<<<NTOK, 128>>>(x, w_gate);
    loss_kernel<<<1, 1>>>(out, out_size);

    split_kernel<<<(NTOK*DIN/4 + 255)/256, 256>>>(x, 0, NTOK*DIN/4);
    split_kernel<<<(DOUT*DIN/4 + 255)/256, 256>>>(static_w, 1, DOUT*DIN/4);
    split_kernel<<<(NEXP*DOUT*DIN/4 + 255)/256, 256>>>(expert_w, 2, NEXP*DOUT*DIN/4);

    dim3 sgrid(DOUT/BN, NTOK/BM);            // 24 x 16
    moe_gemm_mma<false><<<sgrid, 256, SMEM_SZ>>>(out, expert_b);

    dim3 egrid(DOUT/BN, NTOK/BM, NEXP);      // 24 x 16 x 8 (early exit on cnt)
    moe_gemm_mma<true><<<egrid, 256, SMEM_SZ>>>(out, expert_b);
}

// round 4
// speedup vs baseline: 3.2251x; 1.3406x over previous
#include <cuda_runtime.h>
#include <cuda_bf16.h>
#include <cstdint>

// ---------------- problem constants ----------------
#define NTOK 2048      // B*S
#define DIN  768       // D
#define NEXP 8         // E
#define DOUT 3072      // O
#define NO   (NTOK*DOUT)

// ---------------- GEMM tiling ----------------
#define BM 128
#define BN 128
#define BK 32                  // bf16 elems per chunk (64B per row)
#define NCH (DIN/BK)           // 24
#define RSTRIDE 80             // smem row stride in bytes (conflict-free ldmatrix)

// smem layout
#define OFF_TOK 0              // 128 int
#define OFF_GAT 512            // 128 float
#define OFF_ST0 1024
#define AHI 0
#define ALO (128*RSTRIDE)      // 10240
#define BHI (2*128*RSTRIDE)    // 20480
#define BLO (3*128*RSTRIDE)    // 30720
#define STAGE_SZ (4*128*RSTRIDE)   // 40960
#define SMEM_SZ (OFF_ST0 + 2*STAGE_SZ)  // 82944

// ---------------- device scratch ----------------
__device__ int   g_counts[NEXP];
__device__ float g_importance[NEXP];
__device__ int   g_list[NEXP * NTOK];
__device__ float g_gateval[NEXP * NTOK];
__device__ int   g_tokexp[NTOK * 2];     // per-token top-2 expert ids
__device__ float g_tokgate[NTOK * 2];    // per-token top-2 gate values

__device__ __align__(256) __nv_bfloat16 g_xhi[NTOK*DIN];
__device__ __align__(256) __nv_bfloat16 g_xlo[NTOK*DIN];
__device__ __align__(256) __nv_bfloat16 g_cwhi[NEXP*DOUT*DIN];   // expert_w + static_w
__device__ __align__(256) __nv_bfloat16 g_cwlo[NEXP*DOUT*DIN];

// ---------------- PTX helpers (all baseline sm_80+, no 'a' features) -------
__device__ __forceinline__ uint32_t smem_u32(const void* p) {
    uint32_t a;
    asm("{ .reg .u64 t; cvta.to.shared.u64 t, %1; cvt.u32.u64 %0, t; }"
        : "=r"(a) : "l"(p));
    return a;
}
__device__ __forceinline__ void cpasync16(uint32_t dst, const void* src) {
    asm volatile("cp.async.cg.shared.global [%0], [%1], 16;" :: "r"(dst), "l"(src));
}
#define CP_COMMIT() asm volatile("cp.async.commit_group;" ::: "memory")
#define CP_WAIT(n)  asm volatile("cp.async.wait_group %0;" :: "n"(n) : "memory")

__device__ __forceinline__ void ldsm4(uint32_t* r, uint32_t addr) {
    asm volatile("ldmatrix.sync.aligned.m8n8.x4.shared.b16 {%0,%1,%2,%3}, [%4];"
        : "=r"(r[0]), "=r"(r[1]), "=r"(r[2]), "=r"(r[3]) : "r"(addr));
}
__device__ __forceinline__ void mma16816(float* c, const uint32_t* a,
                                         uint32_t b0, uint32_t b1) {
    asm volatile("mma.sync.aligned.m16n8k16.row.col.f32.bf16.bf16.f32 "
        "{%0,%1,%2,%3}, {%4,%5,%6,%7}, {%8,%9}, {%0,%1,%2,%3};"
        : "+f"(c[0]), "+f"(c[1]), "+f"(c[2]), "+f"(c[3])
        : "r"(a[0]), "r"(a[1]), "r"(a[2]), "r"(a[3]), "r"(b0), "r"(b1));
}

// ---------------- kernel: zero counters ----------------
__global__ void zero_kernel() {
    int t = threadIdx.x;
    if (t < NEXP) { g_counts[t] = 0; g_importance[t] = 0.0f; }
}

// ---------------- kernel: gating (one block per token) ----------------
__global__ __launch_bounds__(128)
void gate_kernel(const float* __restrict__ x, const float* __restrict__ wg) {
    int n = blockIdx.x;
    int tid = threadIdx.x;
    float acc[NEXP];
#pragma unroll
    for (int e = 0; e < NEXP; e++) acc[e] = 0.0f;
    const float* xr = x + (size_t)n * DIN;
    for (int d = tid; d < DIN; d += 128) {
        float xv = xr[d];
#pragma unroll
        for (int e = 0; e < NEXP; e++) acc[e] += xv * wg[d * NEXP + e];
    }
    __shared__ float s[128][NEXP];
#pragma unroll
    for (int e = 0; e < NEXP; e++) s[tid][e] = acc[e];
    __syncthreads();
    for (int off = 64; off > 0; off >>= 1) {
        if (tid < off) {
#pragma unroll
            for (int e = 0; e < NEXP; e++) s[tid][e] += s[tid + off][e];
        }
        __syncthreads();
    }
    if (tid == 0) {
        float v[NEXP];
#pragma unroll
        for (int e = 0; e < NEXP; e++) v[e] = s[0][e];
        float best = v[0], second = -3.4e38f;
        int bi = 0, si = -1;
#pragma unroll
        for (int e = 1; e < NEXP; e++) {
            if (v[e] > best)        { second = best; si = bi; best = v[e]; bi = e; }
            else if (v[e] > second) { second = v[e]; si = e; }
        }
        float e1 = __expf(second - best);
        float inv = 1.0f / (1.0f + e1);
        float g0 = inv, g1 = e1 * inv;
        atomicAdd(&g_importance[bi], g0);
        atomicAdd(&g_importance[si], g1);
        int p0 = atomicAdd(&g_counts[bi], 1);
        g_list[bi * NTOK + p0] = n;  g_gateval[bi * NTOK + p0] = g0;
        int p1 = atomicAdd(&g_counts[si], 1);
        g_list[si * NTOK + p1] = n;  g_gateval[si * NTOK + p1] = g1;
        g_tokexp[2*n] = bi;  g_tokexp[2*n+1] = si;
        g_tokgate[2*n] = g0; g_tokgate[2*n+1] = g1;
    }
}

// ---------------- kernel: loss ----------------
__global__ void loss_kernel(float* __restrict__ out, int out_size) {
    if (out_size <= NO) return;
    float mi = 0.0f, ml = 0.0f;
#pragma unroll
    for (int e = 0; e < NEXP; e++) { mi += g_importance[e]; ml += (float)g_counts[e]; }
    mi *= (1.0f / NEXP); ml *= (1.0f / NEXP);
    float vi = 0.0f, vl = 0.0f;
#pragma unroll
    for (int e = 0; e < NEXP; e++) {
        float di = g_importance[e] - mi;    vi += di * di;
        float dl = (float)g_counts[e] - ml; vl += dl * dl;
    }
    vi *= (1.0f / (NEXP - 1)); vl *= (1.0f / (NEXP - 1));
    out[NO] = 0.01f * (vi / (mi * mi + 1e-10f) + vl / (ml * ml + 1e-10f));
}

// ---------------- kernel: x -> bf16 hi/lo split ----------------
__global__ __launch_bounds__(256)
void split_x_kernel(const float* __restrict__ s) {
    int i = blockIdx.x * 256 + threadIdx.x;
    if (i >= NTOK*DIN/4) return;
    float4 v = ((const float4*)s)[i];
    float a[4] = {v.x, v.y, v.z, v.w};
    unsigned short hh[4], ll[4];
#pragma unroll
    for (int k = 0; k < 4; k++) {
        __nv_bfloat16 h = __float2bfloat16(a[k]);
        __nv_bfloat16 l = __float2bfloat16(a[k] - __bfloat162float(h));
        hh[k] = __bfloat16_as_ushort(h);
        ll[k] = __bfloat16_as_ushort(l);
    }
    ((ushort4*)g_xhi)[i] = make_ushort4(hh[0], hh[1], hh[2], hh[3]);
    ((ushort4*)g_xlo)[i] = make_ushort4(ll[0], ll[1], ll[2], ll[3]);
}

// ---------------- kernel: (expert_w + static_w) -> bf16 hi/lo split --------
__global__ __launch_bounds__(256)
void split_cw_kernel(const float* __restrict__ ew, const float* __restrict__ sw) {
    int i = blockIdx.x * 256 + threadIdx.x;
    if (i >= NEXP*DOUT*DIN/4) return;
    int si = i % (DOUT*DIN/4);
    float4 ve = ((const float4*)ew)[i];
    float4 vs = ((const float4*)sw)[si];
    float a[4] = {ve.x + vs.x, ve.y + vs.y, ve.z + vs.z, ve.w + vs.w};
    unsigned short hh[4], ll[4];
#pragma unroll
    for (int k = 0; k < 4; k++) {
        __nv_bfloat16 h = __float2bfloat16(a[k]);
        __nv_bfloat16 l = __float2bfloat16(a[k] - __bfloat162float(h));
        hh[k] = __bfloat16_as_ushort(h);
        ll[k] = __bfloat16_as_ushort(l);
    }
    ((ushort4*)g_cwhi)[i] = make_ushort4(hh[0], hh[1], hh[2], hh[3]);
    ((ushort4*)g_cwlo)[i] = make_ushort4(ll[0], ll[1], ll[2], ll[3]);
}

// ---------------- kernel: init y with gated biases --------------------------
// y[n][o] = g0*b[e0][o] + g1*b[e1][o]   (also clears the poisoned output)
__global__ __launch_bounds__(256)
void init_y_kernel(float* __restrict__ y, const float* __restrict__ eb) {
    int n = blockIdx.y;
    int o = blockIdx.x * 1024 + threadIdx.x * 4;
    int e0 = g_tokexp[2*n], e1 = g_tokexp[2*n+1];
    float g0 = g_tokgate[2*n], g1 = g_tokgate[2*n+1];
    float4 b0 = *(const float4*)(eb + (size_t)e0 * DOUT + o);
    float4 b1 = *(const float4*)(eb + (size_t)e1 * DOUT + o);
    float4 r = { g0*b0.x + g1*b1.x, g0*b0.y + g1*b1.y,
                 g0*b0.z + g1*b1.z, g0*b0.w + g1*b1.w };
    *(float4*)(y + (size_t)n * DOUT + o) = r;
}

// ---------------- kernel: bf16x3 mma.sync expert GEMM ----------------------
// y[tok] += g * (x[tok] . (W_e+sw)^T)   via atomicAdd
__global__ __launch_bounds__(256, 1)
void moe_gemm_mma(float* __restrict__ y) {
    extern __shared__ char sm[];
    uint32_t sb = smem_u32(sm);
    int tid = threadIdx.x, wid = tid >> 5, lane = tid & 31;
    int n0 = blockIdx.x * BN;
    int m0 = blockIdx.y * BM;
    int e  = blockIdx.z;
    int cnt = g_counts[e];
    if (m0 >= cnt) return;

    int* tok_s   = (int*)(sm + OFF_TOK);
    float* gat_s = (float*)(sm + OFF_GAT);
    if (tid < BM) {
        int idx = m0 + tid;
        if (idx < cnt) { tok_s[tid] = g_list[e*NTOK + idx]; gat_s[tid] = g_gateval[e*NTOK + idx]; }
        else           { tok_s[tid] = -1; gat_s[tid] = 0.0f; }
    }
    __syncthreads();

    // ---- cp.async source/dest geometry: 8 x 16B per thread per stage ----
    int c  = tid & 3;                 // 16B chunk in row
    int rr = tid >> 2;                // 0..63
    size_t srcA[2]; size_t srcB[2]; uint32_t dstA[2], dstB[2];
    size_t wbase = (size_t)e * DOUT * DIN;
#pragma unroll
    for (int i = 0; i < 2; i++) {
        int r = rr + i * 64;
        int t = tok_s[r];
        int arow = (t < 0) ? 0 : t;
        srcA[i] = (size_t)arow * DIN + c * 8;
        srcB[i] = wbase + (size_t)(n0 + r) * DIN + c * 8;
        dstA[i] = r * RSTRIDE + c * 16;
        dstB[i] = r * RSTRIDE + c * 16;
    }

    auto load_chunk = [&](int ch, uint32_t stg) {
        int off = ch * BK;
        uint32_t s0 = sb + OFF_ST0 + stg;
#pragma unroll
        for (int i = 0; i < 2; i++) {
            cpasync16(s0 + AHI + dstA[i], g_xhi + srcA[i] + off);
            cpasync16(s0 + ALO + dstA[i], g_xlo + srcA[i] + off);
            cpasync16(s0 + BHI + dstB[i], g_cwhi + srcB[i] + off);
            cpasync16(s0 + BLO + dstB[i], g_cwlo + srcB[i] + off);
        }
        CP_COMMIT();
    };

    // ---- ldmatrix per-lane base offsets ----
    int wm = (wid >> 2) * 64;         // warp m origin (2 warps)
    int wn = (wid & 3) * 32;          // warp n origin (4 warps)
    int mat = lane >> 3, r8 = lane & 7;
    uint32_t aoff = (uint32_t)((wm + (mat & 1) * 8 + r8) * RSTRIDE + (mat >> 1) * 16);
    uint32_t boff = (uint32_t)((wn + ((mat >> 1) & 1) * 8 + r8) * RSTRIDE + (mat & 1) * 16);

    float acc[4][4][4] = {};

    load_chunk(0, 0);
    for (int ch = 0; ch < NCH; ch++) {
        uint32_t stg = (uint32_t)(ch & 1) * STAGE_SZ;
        if (ch + 1 < NCH) {
            load_chunk(ch + 1, (uint32_t)((ch + 1) & 1) * STAGE_SZ);
            CP_WAIT(1);
        } else {
            CP_WAIT(0);
        }
        __syncthreads();

        uint32_t aHi = sb + OFF_ST0 + stg + AHI + aoff;
        uint32_t aLo = sb + OFF_ST0 + stg + ALO + aoff;
        uint32_t bHi = sb + OFF_ST0 + stg + BHI + boff;
        uint32_t bLo = sb + OFF_ST0 + stg + BLO + boff;

#pragma unroll
        for (int ks = 0; ks < 2; ks++) {
            uint32_t ah[4][4], al[4][4], bh[2][4], bl[2][4];
#pragma unroll
            for (int mi = 0; mi < 4; mi++) {
                ldsm4(ah[mi], aHi + mi * (16 * RSTRIDE) + ks * 32);
                ldsm4(al[mi], aLo + mi * (16 * RSTRIDE) + ks * 32);
            }
#pragma unroll
            for (int nt = 0; nt < 2; nt++) {
                ldsm4(bh[nt], bHi + nt * (16 * RSTRIDE) + ks * 32);
                ldsm4(bl[nt], bLo + nt * (16 * RSTRIDE) + ks * 32);
            }
#pragma unroll
            for (int mi = 0; mi < 4; mi++) {
#pragma unroll
                for (int nj = 0; nj < 4; nj++) {
                    uint32_t h0 = bh[nj >> 1][(nj & 1) * 2];
                    uint32_t h1 = bh[nj >> 1][(nj & 1) * 2 + 1];
                    uint32_t l0 = bl[nj >> 1][(nj & 1) * 2];
                    uint32_t l1 = bl[nj >> 1][(nj & 1) * 2 + 1];
                    mma16816(acc[mi][nj], ah[mi], h0, h1);   // hi*hi
                    mma16816(acc[mi][nj], ah[mi], l0, l1);   // hi*lo
                    mma16816(acc[mi][nj], al[mi], h0, h1);   // lo*hi
                }
            }
        }
        __syncthreads();
    }

    // ---- epilogue: y[tok] += g * acc ----
    int t4r = lane >> 2;                  // 0..7
    int t4c = (lane & 3) * 2;             // 0,2,4,6
#pragma unroll
    for (int mi = 0; mi < 4; mi++) {
#pragma unroll
        for (int half = 0; half < 2; half++) {
            int r = wm + mi * 16 + half * 8 + t4r;          // tile row 0..127
            int tok = tok_s[r];
            if (tok < 0) continue;
            float g = gat_s[r];
            float* yr = y + (size_t)tok * DOUT + n0;
#pragma unroll
            for (int nj = 0; nj < 4; nj++) {
                int cn = wn + nj * 8 + t4c;
                atomicAdd(yr + cn,     g * acc[mi][nj][half*2]);
                atomicAdd(yr + cn + 1, g * acc[mi][nj][half*2+1]);
            }
        }
    }
}

// ---------------- launch ----------------
extern "C" void kernel_launch(void* const* d_in, const int* in_sizes, int n_in,
                              void* d_out, int out_size) {
    const float* x        = (const float*)d_in[0];   // [2048, 768]
    const float* w_gate   = (const float*)d_in[1];   // [768, 8]
    const float* expert_w = (const float*)d_in[2];   // [8, 3072, 768]
    const float* expert_b = (const float*)d_in[3];   // [8, 3072]
    const float* static_w = (const float*)d_in[4];   // [3072, 768]
    float* out = (float*)d_out;

    cudaFuncSetAttribute(moe_gemm_mma, cudaFuncAttributeMaxDynamicSharedMemorySize, SMEM_SZ);

    zero_kernel<<<1, 32>>>();
    gate_kernel<<<NTOK, 128>>>(x, w_gate);
    loss_kernel<<<1, 1>>>(out, out_size);

    split_x_kernel<<<(NTOK*DIN/4 + 255)/256, 256>>>(x);
    split_cw_kernel<<<(NEXP*DOUT*DIN/4 + 255)/256, 256>>>(expert_w, static_w);

    dim3 igrid(DOUT/1024, NTOK);             // 3 x 2048
    init_y_kernel<<<igrid, 256>>>(out, expert_b);

    dim3 egrid(DOUT/BN, NTOK/BM, NEXP);      // 24 x 16 x 8 (early exit on cnt)
    moe_gemm_mma<<<egrid, 256, SMEM_SZ>>>(out);
}

// round 5
// speedup vs baseline: 3.2453x; 1.0063x over previous
#include <cuda_runtime.h>
#include <cuda_bf16.h>
#include <cstdint>

// ---------------- problem constants ----------------
#define NTOK 2048      // B*S
#define DIN  768       // D
#define NEXP 8         // E
#define DOUT 3072      // O
#define NO   (NTOK*DOUT)

// ---------------- GEMM tiling ----------------
#define BM 128
#define BN 256
#define BK 32                  // bf16 elems per chunk (64B per row)
#define NCH (DIN/BK)           // 24
#define RSTRIDE 80             // smem row stride bytes (conflict-free ldmatrix)
#define NSTAGE 3

// smem layout
#define OFF_TOK 0              // 128 int
#define OFF_GAT 512            // 128 float
#define OFF_ST0 1024
#define AHI 0
#define ALO (128*RSTRIDE)          // 10240
#define BHI (2*128*RSTRIDE)        // 20480
#define BLO (2*128*RSTRIDE + 256*RSTRIDE)  // 40960
#define STAGE_SZ (2*128*RSTRIDE + 2*256*RSTRIDE)   // 61440
#define SMEM_SZ (OFF_ST0 + NSTAGE*STAGE_SZ)        // 185344

// ---------------- device scratch ----------------
__device__ int   g_counts[NEXP];
__device__ float g_importance[NEXP];
__device__ int   g_list[NEXP * NTOK];
__device__ float g_gateval[NEXP * NTOK];
__device__ int   g_tokexp[NTOK * 2];
__device__ float g_tokgate[NTOK * 2];

__device__ __align__(256) __nv_bfloat16 g_xhi[NTOK*DIN];
__device__ __align__(256) __nv_bfloat16 g_xlo[NTOK*DIN];
__device__ __align__(256) __nv_bfloat16 g_cwhi[NEXP*DOUT*DIN];   // expert_w + static_w
__device__ __align__(256) __nv_bfloat16 g_cwlo[NEXP*DOUT*DIN];

// ---------------- PTX helpers (baseline sm_80+, no 'a' features) ----------
__device__ __forceinline__ uint32_t smem_u32(const void* p) {
    uint32_t a;
    asm("{ .reg .u64 t; cvta.to.shared.u64 t, %1; cvt.u32.u64 %0, t; }"
        : "=r"(a) : "l"(p));
    return a;
}
__device__ __forceinline__ void cpasync16(uint32_t dst, const void* src) {
    asm volatile("cp.async.cg.shared.global [%0], [%1], 16;" :: "r"(dst), "l"(src));
}
#define CP_COMMIT() asm volatile("cp.async.commit_group;" ::: "memory")
#define CP_WAIT(n)  asm volatile("cp.async.wait_group %0;" :: "n"(n) : "memory")

__device__ __forceinline__ void ldsm4(uint32_t* r, uint32_t addr) {
    asm volatile("ldmatrix.sync.aligned.m8n8.x4.shared.b16 {%0,%1,%2,%3}, [%4];"
        : "=r"(r[0]), "=r"(r[1]), "=r"(r[2]), "=r"(r[3]) : "r"(addr));
}
__device__ __forceinline__ void mma16816(float* c, const uint32_t* a,
                                         uint32_t b0, uint32_t b1) {
    asm volatile("mma.sync.aligned.m16n8k16.row.col.f32.bf16.bf16.f32 "
        "{%0,%1,%2,%3}, {%4,%5,%6,%7}, {%8,%9}, {%0,%1,%2,%3};"
        : "+f"(c[0]), "+f"(c[1]), "+f"(c[2]), "+f"(c[3])
        : "r"(a[0]), "r"(a[1]), "r"(a[2]), "r"(a[3]), "r"(b0), "r"(b1));
}

// ---------------- kernel: zero counters ----------------
__global__ void zero_kernel() {
    int t = threadIdx.x;
    if (t < NEXP) { g_counts[t] = 0; g_importance[t] = 0.0f; }
}

// ---------------- kernel: gating (one WARP per token) ----------------
__global__ __launch_bounds__(256)
void gate_kernel(const float* __restrict__ x, const float* __restrict__ wg) {
    int gw   = (blockIdx.x * 256 + threadIdx.x) >> 5;   // global warp = token
    int lane = threadIdx.x & 31;
    if (gw >= NTOK) return;

    const float4* xr = (const float4*)(x + (size_t)gw * DIN);
    float acc[NEXP];
#pragma unroll
    for (int e = 0; e < NEXP; e++) acc[e] = 0.0f;

#pragma unroll
    for (int it = 0; it < DIN/4/32; it++) {             // 6 iters
        int i = it * 32 + lane;
        float4 v = xr[i];
        const float* w0 = wg + (size_t)(i * 4) * NEXP;
#pragma unroll
        for (int e = 0; e < NEXP; e++)
            acc[e] += v.x * w0[e] + v.y * w0[NEXP + e]
                    + v.z * w0[2*NEXP + e] + v.w * w0[3*NEXP + e];
    }
#pragma unroll
    for (int e = 0; e < NEXP; e++) {
#pragma unroll
        for (int off = 16; off > 0; off >>= 1)
            acc[e] += __shfl_xor_sync(0xffffffffu, acc[e], off);
    }
    if (lane == 0) {
        float best = acc[0], second = -3.4e38f;
        int bi = 0, si = -1;
#pragma unroll
        for (int e = 1; e < NEXP; e++) {
            if (acc[e] > best)        { second = best; si = bi; best = acc[e]; bi = e; }
            else if (acc[e] > second) { second = acc[e]; si = e; }
        }
        float e1 = __expf(second - best);
        float inv = 1.0f / (1.0f + e1);
        float g0 = inv, g1 = e1 * inv;
        atomicAdd(&g_importance[bi], g0);
        atomicAdd(&g_importance[si], g1);
        int p0 = atomicAdd(&g_counts[bi], 1);
        g_list[bi * NTOK + p0] = gw;  g_gateval[bi * NTOK + p0] = g0;
        int p1 = atomicAdd(&g_counts[si], 1);
        g_list[si * NTOK + p1] = gw;  g_gateval[si * NTOK + p1] = g1;
        g_tokexp[2*gw] = bi;  g_tokexp[2*gw+1] = si;
        g_tokgate[2*gw] = g0; g_tokgate[2*gw+1] = g1;
    }
}

// ---------------- kernel: loss ----------------
__global__ void loss_kernel(float* __restrict__ out, int out_size) {
    if (out_size <= NO) return;
    float mi = 0.0f, ml = 0.0f;
#pragma unroll
    for (int e = 0; e < NEXP; e++) { mi += g_importance[e]; ml += (float)g_counts[e]; }
    mi *= (1.0f / NEXP); ml *= (1.0f / NEXP);
    float vi = 0.0f, vl = 0.0f;
#pragma unroll
    for (int e = 0; e < NEXP; e++) {
        float di = g_importance[e] - mi;    vi += di * di;
        float dl = (float)g_counts[e] - ml; vl += dl * dl;
    }
    vi *= (1.0f / (NEXP - 1)); vl *= (1.0f / (NEXP - 1));
    out[NO] = 0.01f * (vi / (mi * mi + 1e-10f) + vl / (ml * ml + 1e-10f));
}

// ---------------- split helpers ----------------
__device__ __forceinline__ void split4(const float4 v, ushort4& h4, ushort4& l4) {
    float a[4] = {v.x, v.y, v.z, v.w};
    unsigned short hh[4], ll[4];
#pragma unroll
    for (int k = 0; k < 4; k++) {
        __nv_bfloat16 h = __float2bfloat16(a[k]);
        __nv_bfloat16 l = __float2bfloat16(a[k] - __bfloat162float(h));
        hh[k] = __bfloat16_as_ushort(h);
        ll[k] = __bfloat16_as_ushort(l);
    }
    h4 = make_ushort4(hh[0], hh[1], hh[2], hh[3]);
    l4 = make_ushort4(ll[0], ll[1], ll[2], ll[3]);
}

// ---------------- kernel: x -> bf16 hi/lo split ----------------
__global__ __launch_bounds__(256)
void split_x_kernel(const float* __restrict__ s) {
    int i = blockIdx.x * 256 + threadIdx.x;
    if (i >= NTOK*DIN/4) return;
    ushort4 h4, l4;
    split4(((const float4*)s)[i], h4, l4);
    ((ushort4*)g_xhi)[i] = h4;
    ((ushort4*)g_xlo)[i] = l4;
}

// ---------------- kernel: (expert_w + static_w) -> bf16 hi/lo, 8/thread ----
__global__ __launch_bounds__(256)
void split_cw_kernel(const float* __restrict__ ew, const float* __restrict__ sw) {
    int i = (blockIdx.x * 256 + threadIdx.x) * 2;      // float4 index, 2 per thread
    if (i >= NEXP*DOUT*DIN/4) return;
    int si = i % (DOUT*DIN/4);
#pragma unroll
    for (int u = 0; u < 2; u++) {
        float4 ve = ((const float4*)ew)[i + u];
        float4 vs = ((const float4*)sw)[si + u];
        float4 v = { ve.x + vs.x, ve.y + vs.y, ve.z + vs.z, ve.w + vs.w };
        ushort4 h4, l4;
        split4(v, h4, l4);
        ((ushort4*)g_cwhi)[i + u] = h4;
        ((ushort4*)g_cwlo)[i + u] = l4;
    }
}

// ---------------- kernel: init y with gated biases --------------------------
__global__ __launch_bounds__(256)
void init_y_kernel(float* __restrict__ y, const float* __restrict__ eb) {
    int n = blockIdx.y;
    int o = blockIdx.x * 1024 + threadIdx.x * 4;
    int e0 = g_tokexp[2*n], e1 = g_tokexp[2*n+1];
    float g0 = g_tokgate[2*n], g1 = g_tokgate[2*n+1];
    float4 b0 = *(const float4*)(eb + (size_t)e0 * DOUT + o);
    float4 b1 = *(const float4*)(eb + (size_t)e1 * DOUT + o);
    float4 r = { g0*b0.x + g1*b1.x, g0*b0.y + g1*b1.y,
                 g0*b0.z + g1*b1.z, g0*b0.w + g1*b1.w };
    *(float4*)(y + (size_t)n * DOUT + o) = r;
}

// ---------------- kernel: bf16x3 mma.sync expert GEMM ----------------------
// 512 threads, 16 warps (2 m-rows x 8 n-cols of 64x32 warp tiles), 3-stage.
__global__ __launch_bounds__(512, 1)
void moe_gemm_mma(float* __restrict__ y) {
    extern __shared__ char sm[];
    uint32_t sb = smem_u32(sm);
    int tid = threadIdx.x, wid = tid >> 5, lane = tid & 31;
    int n0 = blockIdx.x * BN;
    int m0 = blockIdx.y * BM;
    int e  = blockIdx.z;
    int cnt = g_counts[e];
    if (m0 >= cnt) return;

    int* tok_s   = (int*)(sm + OFF_TOK);
    float* gat_s = (float*)(sm + OFF_GAT);
    if (tid < BM) {
        int idx = m0 + tid;
        if (idx < cnt) { tok_s[tid] = g_list[e*NTOK + idx]; gat_s[tid] = g_gateval[e*NTOK + idx]; }
        else           { tok_s[tid] = -1; gat_s[tid] = 0.0f; }
    }
    __syncthreads();

    // ---- cp.async geometry: 6 x 16B per thread per stage ----
    int c  = tid & 3;                 // 16B chunk in 64B row
    int rr = tid >> 2;                // 0..127
    int ta = tok_s[rr];
    size_t srcA = (size_t)((ta < 0) ? 0 : ta) * DIN + c * 8;
    size_t wbase = (size_t)e * DOUT * DIN;
    size_t srcB0 = wbase + (size_t)(n0 + rr) * DIN + c * 8;
    size_t srcB1 = wbase + (size_t)(n0 + rr + 128) * DIN + c * 8;
    uint32_t dstA  = rr * RSTRIDE + c * 16;
    uint32_t dstB0 = rr * RSTRIDE + c * 16;
    uint32_t dstB1 = (rr + 128) * RSTRIDE + c * 16;

    auto load_chunk = [&](int ch, uint32_t stg) {
        int off = ch * BK;
        uint32_t s0 = sb + OFF_ST0 + stg;
        cpasync16(s0 + AHI + dstA,  g_xhi  + srcA  + off);
        cpasync16(s0 + ALO + dstA,  g_xlo  + srcA  + off);
        cpasync16(s0 + BHI + dstB0, g_cwhi + srcB0 + off);
        cpasync16(s0 + BLO + dstB0, g_cwlo + srcB0 + off);
        cpasync16(s0 + BHI + dstB1, g_cwhi + srcB1 + off);
        cpasync16(s0 + BLO + dstB1, g_cwlo + srcB1 + off);
        CP_COMMIT();
    };

    // ---- ldmatrix per-lane base offsets (warp tile 64x32, 2x8 warps) ----
    int wm = (wid >> 3) * 64;         // 0 or 64
    int wn = (wid & 7) * 32;          // 0..224
    int mat = lane >> 3, r8 = lane & 7;
    uint32_t aoff = (uint32_t)((wm + (mat & 1) * 8 + r8) * RSTRIDE + (mat >> 1) * 16);
    uint32_t boff = (uint32_t)((wn + ((mat >> 1) & 1) * 8 + r8) * RSTRIDE + (mat & 1) * 16);

    float acc[4][4][4] = {};

    load_chunk(0, 0);
    load_chunk(1, STAGE_SZ);

    uint32_t stg = 0;
    for (int ch = 0; ch < NCH; ch++) {
        if (ch < NCH - 1) { CP_WAIT(1); } else { CP_WAIT(0); }
        __syncthreads();
        if (ch + 2 < NCH) {
            uint32_t nst = stg + 2*STAGE_SZ;
            if (nst >= (uint32_t)NSTAGE*STAGE_SZ) nst -= NSTAGE*STAGE_SZ;
            load_chunk(ch + 2, nst);
        }

        uint32_t aHi = sb + OFF_ST0 + stg + AHI + aoff;
        uint32_t aLo = sb + OFF_ST0 + stg + ALO + aoff;
        uint32_t bHi = sb + OFF_ST0 + stg + BHI + boff;
        uint32_t bLo = sb + OFF_ST0 + stg + BLO + boff;

#pragma unroll
        for (int ks = 0; ks < 2; ks++) {
            uint32_t ah[4][4], al[4][4], bh[2][4], bl[2][4];
#pragma unroll
            for (int mi = 0; mi < 4; mi++) {
                ldsm4(ah[mi], aHi + mi * (16 * RSTRIDE) + ks * 32);
                ldsm4(al[mi], aLo + mi * (16 * RSTRIDE) + ks * 32);
            }
#pragma unroll
            for (int nt = 0; nt < 2; nt++) {
                ldsm4(bh[nt], bHi + nt * (16 * RSTRIDE) + ks * 32);
                ldsm4(bl[nt], bLo + nt * (16 * RSTRIDE) + ks * 32);
            }
#pragma unroll
            for (int mi = 0; mi < 4; mi++) {
#pragma unroll
                for (int nj = 0; nj < 4; nj++) {
                    uint32_t h0 = bh[nj >> 1][(nj & 1) * 2];
                    uint32_t h1 = bh[nj >> 1][(nj & 1) * 2 + 1];
                    uint32_t l0 = bl[nj >> 1][(nj & 1) * 2];
                    uint32_t l1 = bl[nj >> 1][(nj & 1) * 2 + 1];
                    mma16816(acc[mi][nj], ah[mi], h0, h1);   // hi*hi
                    mma16816(acc[mi][nj], ah[mi], l0, l1);   // hi*lo
                    mma16816(acc[mi][nj], al[mi], h0, h1);   // lo*hi
                }
            }
        }
        stg += STAGE_SZ;
        if (stg >= (uint32_t)NSTAGE*STAGE_SZ) stg = 0;
    }

    // ---- epilogue: y[tok] += g * acc ----
    int t4r = lane >> 2;
    int t4c = (lane & 3) * 2;
#pragma unroll
    for (int mi = 0; mi < 4; mi++) {
#pragma unroll
        for (int half = 0; half < 2; half++) {
            int r = wm + mi * 16 + half * 8 + t4r;
            int tok = tok_s[r];
            if (tok < 0) continue;
            float g = gat_s[r];
            float* yr = y + (size_t)tok * DOUT + n0;
#pragma unroll
            for (int nj = 0; nj < 4; nj++) {
                int cn = wn + nj * 8 + t4c;
                atomicAdd(yr + cn,     g * acc[mi][nj][half*2]);
                atomicAdd(yr + cn + 1, g * acc[mi][nj][half*2+1]);
            }
        }
    }
}

// ---------------- launch ----------------
extern "C" void kernel_launch(void* const* d_in, const int* in_sizes, int n_in,
                              void* d_out, int out_size) {
    const float* x        = (const float*)d_in[0];   // [2048, 768]
    const float* w_gate   = (const float*)d_in[1];   // [768, 8]
    const float* expert_w = (const float*)d_in[2];   // [8, 3072, 768]
    const float* expert_b = (const float*)d_in[3];   // [8, 3072]
    const float* static_w = (const float*)d_in[4];   // [3072, 768]
    float* out = (float*)d_out;

    cudaFuncSetAttribute(moe_gemm_mma, cudaFuncAttributeMaxDynamicSharedMemorySize, SMEM_SZ);

    zero_kernel<<<1, 32>>>();
    gate_kernel<<<NTOK/8, 256>>>(x, w_gate);
    loss_kernel<<<1, 1>>>(out, out_size);

    split_x_kernel<<<(NTOK*DIN/4 + 255)/256, 256>>>(x);
    split_cw_kernel<<<(NEXP*DOUT*DIN/8 + 255)/256, 256>>>(expert_w, static_w);

    dim3 igrid(DOUT/1024, NTOK);             // 3 x 2048
    init_y_kernel<<<igrid, 256>>>(out, expert_b);

    dim3 egrid(DOUT/BN, NTOK/BM, NEXP);      // 12 x 16 x 8 (early exit on cnt)
    moe_gemm_mma<<<egrid, 512, SMEM_SZ>>>(out);
}

// round 6
// speedup vs baseline: 4.9351x; 1.5207x over previous
#include <cuda_runtime.h>
#include <cuda_bf16.h>
#include <cuda_fp16.h>
#include <cstdint>

// ---------------- problem constants ----------------
#define NTOK 2048      // B*S
#define DIN  768       // D
#define NEXP 8         // E
#define DOUT 3072      // O
#define NO   (NTOK*DOUT)

// ---------------- GEMM tiling ----------------
#define BM 128
#define BN 256
#define BK 32                  // fp16 elems per chunk (64B per row)
#define NCH (DIN/BK)           // 24
#define RSTRIDE 80             // smem row stride bytes (conflict-free ldmatrix)
#define NSTAGE 3

// smem layout
#define OFF_TOK 0              // 128 int
#define OFF_GAT 512            // 128 float
#define OFF_ST0 1024
#define AOFFS 0
#define BOFFS (128*RSTRIDE)                 // 10240
#define STAGE_SZ (128*RSTRIDE + 256*RSTRIDE)   // 30720
#define SMEM_SZ (OFF_ST0 + NSTAGE*STAGE_SZ)    // 93184

// ---------------- device scratch ----------------
__device__ int   g_counts[NEXP];
__device__ float g_importance[NEXP];
__device__ int   g_list[NEXP * NTOK];
__device__ float g_gateval[NEXP * NTOK];
__device__ int   g_tokexp[NTOK * 2];
__device__ float g_tokgate[NTOK * 2];

__device__ __align__(256) __half g_xh[NTOK*DIN];
__device__ __align__(256) __half g_cwh[NEXP*DOUT*DIN];   // fp16(expert_w + static_w)

// ---------------- PTX helpers (baseline sm_80+, no 'a' features) ----------
__device__ __forceinline__ uint32_t smem_u32(const void* p) {
    uint32_t a;
    asm("{ .reg .u64 t; cvta.to.shared.u64 t, %1; cvt.u32.u64 %0, t; }"
        : "=r"(a) : "l"(p));
    return a;
}
__device__ __forceinline__ void cpasync16(uint32_t dst, const void* src) {
    asm volatile("cp.async.cg.shared.global [%0], [%1], 16;" :: "r"(dst), "l"(src));
}
#define CP_COMMIT() asm volatile("cp.async.commit_group;" ::: "memory")
#define CP_WAIT(n)  asm volatile("cp.async.wait_group %0;" :: "n"(n) : "memory")

__device__ __forceinline__ void ldsm4(uint32_t* r, uint32_t addr) {
    asm volatile("ldmatrix.sync.aligned.m8n8.x4.shared.b16 {%0,%1,%2,%3}, [%4];"
        : "=r"(r[0]), "=r"(r[1]), "=r"(r[2]), "=r"(r[3]) : "r"(addr));
}
__device__ __forceinline__ void mma16816(float* c, const uint32_t* a,
                                         uint32_t b0, uint32_t b1) {
    asm volatile("mma.sync.aligned.m16n8k16.row.col.f32.f16.f16.f32 "
        "{%0,%1,%2,%3}, {%4,%5,%6,%7}, {%8,%9}, {%0,%1,%2,%3};"
        : "+f"(c[0]), "+f"(c[1]), "+f"(c[2]), "+f"(c[3])
        : "r"(a[0]), "r"(a[1]), "r"(a[2]), "r"(a[3]), "r"(b0), "r"(b1));
}

// ---------------- kernel: zero counters ----------------
__global__ void zero_kernel() {
    int t = threadIdx.x;
    if (t < NEXP) { g_counts[t] = 0; g_importance[t] = 0.0f; }
}

// ---------------- kernel: gating (one WARP per token) ----------------
__global__ __launch_bounds__(256)
void gate_kernel(const float* __restrict__ x, const float* __restrict__ wg) {
    int gw   = (blockIdx.x * 256 + threadIdx.x) >> 5;   // global warp = token
    int lane = threadIdx.x & 31;
    if (gw >= NTOK) return;

    const float4* xr = (const float4*)(x + (size_t)gw * DIN);
    float acc[NEXP];
#pragma unroll
    for (int e = 0; e < NEXP; e++) acc[e] = 0.0f;

#pragma unroll
    for (int it = 0; it < DIN/4/32; it++) {             // 6 iters
        int i = it * 32 + lane;
        float4 v = xr[i];
        const float* w0 = wg + (size_t)(i * 4) * NEXP;
#pragma unroll
        for (int e = 0; e < NEXP; e++)
            acc[e] += v.x * w0[e] + v.y * w0[NEXP + e]
                    + v.z * w0[2*NEXP + e] + v.w * w0[3*NEXP + e];
    }
#pragma unroll
    for (int e = 0; e < NEXP; e++) {
#pragma unroll
        for (int off = 16; off > 0; off >>= 1)
            acc[e] += __shfl_xor_sync(0xffffffffu, acc[e], off);
    }
    if (lane == 0) {
        float best = acc[0], second = -3.4e38f;
        int bi = 0, si = -1;
#pragma unroll
        for (int e = 1; e < NEXP; e++) {
            if (acc[e] > best)        { second = best; si = bi; best = acc[e]; bi = e; }
            else if (acc[e] > second) { second = acc[e]; si = e; }
        }
        float e1 = __expf(second - best);
        float inv = 1.0f / (1.0f + e1);
        float g0 = inv, g1 = e1 * inv;
        atomicAdd(&g_importance[bi], g0);
        atomicAdd(&g_importance[si], g1);
        int p0 = atomicAdd(&g_counts[bi], 1);
        g_list[bi * NTOK + p0] = gw;  g_gateval[bi * NTOK + p0] = g0;
        int p1 = atomicAdd(&g_counts[si], 1);
        g_list[si * NTOK + p1] = gw;  g_gateval[si * NTOK + p1] = g1;
        g_tokexp[2*gw] = bi;  g_tokexp[2*gw+1] = si;
        g_tokgate[2*gw] = g0; g_tokgate[2*gw+1] = g1;
    }
}

// ---------------- kernel: loss ----------------
__global__ void loss_kernel(float* __restrict__ out, int out_size) {
    if (out_size <= NO) return;
    float mi = 0.0f, ml = 0.0f;
#pragma unroll
    for (int e = 0; e < NEXP; e++) { mi += g_importance[e]; ml += (float)g_counts[e]; }
    mi *= (1.0f / NEXP); ml *= (1.0f / NEXP);
    float vi = 0.0f, vl = 0.0f;
#pragma unroll
    for (int e = 0; e < NEXP; e++) {
        float di = g_importance[e] - mi;    vi += di * di;
        float dl = (float)g_counts[e] - ml; vl += dl * dl;
    }
    vi *= (1.0f / (NEXP - 1)); vl *= (1.0f / (NEXP - 1));
    out[NO] = 0.01f * (vi / (mi * mi + 1e-10f) + vl / (ml * ml + 1e-10f));
}

// ---------------- fp32x8 -> fp16x8 pack ----------------
__device__ __forceinline__ uint4 cvt8(const float4 a, const float4 b) {
    __half2 h0 = __floats2half2_rn(a.x, a.y);
    __half2 h1 = __floats2half2_rn(a.z, a.w);
    __half2 h2 = __floats2half2_rn(b.x, b.y);
    __half2 h3 = __floats2half2_rn(b.z, b.w);
    uint4 r;
    r.x = *(uint32_t*)&h0; r.y = *(uint32_t*)&h1;
    r.z = *(uint32_t*)&h2; r.w = *(uint32_t*)&h3;
    return r;
}

// ---------------- kernel: x -> fp16 ----------------
__global__ __launch_bounds__(256)
void split_x_kernel(const float* __restrict__ s) {
    int i = blockIdx.x * 256 + threadIdx.x;       // 8 elems per thread
    if (i >= NTOK*DIN/8) return;
    float4 a = ((const float4*)s)[2*i];
    float4 b = ((const float4*)s)[2*i + 1];
    ((uint4*)g_xh)[i] = cvt8(a, b);
}

// ---------------- kernel: fp16(expert_w + static_w) ----------------
__global__ __launch_bounds__(256)
void split_cw_kernel(const float* __restrict__ ew, const float* __restrict__ sw) {
    int i = blockIdx.x * 256 + threadIdx.x;       // 8 elems per thread
    if (i >= NEXP*DOUT*DIN/8) return;
    int si = i % (DOUT*DIN/8);
    float4 ea = ((const float4*)ew)[2*i];
    float4 eb = ((const float4*)ew)[2*i + 1];
    float4 sa = ((const float4*)sw)[2*si];
    float4 sb = ((const float4*)sw)[2*si + 1];
    float4 a = { ea.x + sa.x, ea.y + sa.y, ea.z + sa.z, ea.w + sa.w };
    float4 b = { eb.x + sb.x, eb.y + sb.y, eb.z + sb.z, eb.w + sb.w };
    ((uint4*)g_cwh)[i] = cvt8(a, b);
}

// ---------------- kernel: init y with gated biases --------------------------
__global__ __launch_bounds__(256)
void init_y_kernel(float* __restrict__ y, const float* __restrict__ eb) {
    int n = blockIdx.y;
    int o = blockIdx.x * 1024 + threadIdx.x * 4;
    int e0 = g_tokexp[2*n], e1 = g_tokexp[2*n+1];
    float g0 = g_tokgate[2*n], g1 = g_tokgate[2*n+1];
    float4 b0 = *(const float4*)(eb + (size_t)e0 * DOUT + o);
    float4 b1 = *(const float4*)(eb + (size_t)e1 * DOUT + o);
    float4 r = { g0*b0.x + g1*b1.x, g0*b0.y + g1*b1.y,
                 g0*b0.z + g1*b1.z, g0*b0.w + g1*b1.w };
    *(float4*)(y + (size_t)n * DOUT + o) = r;
}

// ---------------- kernel: fp16 mma.sync expert GEMM ------------------------
// 512 threads, 16 warps (2 m-rows x 8 n-cols of 64x32 warp tiles), 3-stage.
__global__ __launch_bounds__(512, 1)
void moe_gemm_mma(float* __restrict__ y) {
    extern __shared__ char sm[];
    uint32_t sb = smem_u32(sm);
    int tid = threadIdx.x, wid = tid >> 5, lane = tid & 31;
    int n0 = blockIdx.x * BN;
    int m0 = blockIdx.y * BM;
    int e  = blockIdx.z;
    int cnt = g_counts[e];
    if (m0 >= cnt) return;

    int* tok_s   = (int*)(sm + OFF_TOK);
    float* gat_s = (float*)(sm + OFF_GAT);
    if (tid < BM) {
        int idx = m0 + tid;
        if (idx < cnt) { tok_s[tid] = g_list[e*NTOK + idx]; gat_s[tid] = g_gateval[e*NTOK + idx]; }
        else           { tok_s[tid] = -1; gat_s[tid] = 0.0f; }
    }
    __syncthreads();

    // ---- cp.async geometry: 3 x 16B per thread per stage ----
    int c  = tid & 3;                 // 16B chunk in 64B row
    int rr = tid >> 2;                // 0..127
    int ta = tok_s[rr];
    size_t srcA = (size_t)((ta < 0) ? 0 : ta) * DIN + c * 8;
    size_t wbase = (size_t)e * DOUT * DIN;
    size_t srcB0 = wbase + (size_t)(n0 + rr) * DIN + c * 8;
    size_t srcB1 = wbase + (size_t)(n0 + rr + 128) * DIN + c * 8;
    uint32_t dstA  = rr * RSTRIDE + c * 16;
    uint32_t dstB0 = rr * RSTRIDE + c * 16;
    uint32_t dstB1 = (rr + 128) * RSTRIDE + c * 16;

    auto load_chunk = [&](int ch, uint32_t stg) {
        int off = ch * BK;
        uint32_t s0 = sb + OFF_ST0 + stg;
        cpasync16(s0 + AOFFS + dstA,  g_xh  + srcA  + off);
        cpasync16(s0 + BOFFS + dstB0, g_cwh + srcB0 + off);
        cpasync16(s0 + BOFFS + dstB1, g_cwh + srcB1 + off);
        CP_COMMIT();
    };

    // ---- ldmatrix per-lane base offsets (warp tile 64x32, 2x8 warps) ----
    int wm = (wid >> 3) * 64;         // 0 or 64
    int wn = (wid & 7) * 32;          // 0..224
    int mat = lane >> 3, r8 = lane & 7;
    uint32_t aoff = (uint32_t)((wm + (mat & 1) * 8 + r8) * RSTRIDE + (mat >> 1) * 16);
    uint32_t boff = (uint32_t)((wn + ((mat >> 1) & 1) * 8 + r8) * RSTRIDE + (mat & 1) * 16);

    float acc[4][4][4] = {};

    load_chunk(0, 0);
    load_chunk(1, STAGE_SZ);

    uint32_t stg = 0;
    for (int ch = 0; ch < NCH; ch++) {
        if (ch < NCH - 1) { CP_WAIT(1); } else { CP_WAIT(0); }
        __syncthreads();
        if (ch + 2 < NCH) {
            uint32_t nst = stg + 2*STAGE_SZ;
            if (nst >= (uint32_t)NSTAGE*STAGE_SZ) nst -= NSTAGE*STAGE_SZ;
            load_chunk(ch + 2, nst);
        }

        uint32_t aBase = sb + OFF_ST0 + stg + AOFFS + aoff;
        uint32_t bBase = sb + OFF_ST0 + stg + BOFFS + boff;

#pragma unroll
        for (int ks = 0; ks < 2; ks++) {
            uint32_t ah[4][4], bh[2][4];
#pragma unroll
            for (int mi = 0; mi < 4; mi++)
                ldsm4(ah[mi], aBase + mi * (16 * RSTRIDE) + ks * 32);
#pragma unroll
            for (int nt = 0; nt < 2; nt++)
                ldsm4(bh[nt], bBase + nt * (16 * RSTRIDE) + ks * 32);
#pragma unroll
            for (int mi = 0; mi < 4; mi++) {
#pragma unroll
                for (int nj = 0; nj < 4; nj++) {
                    uint32_t h0 = bh[nj >> 1][(nj & 1) * 2];
                    uint32_t h1 = bh[nj >> 1][(nj & 1) * 2 + 1];
                    mma16816(acc[mi][nj], ah[mi], h0, h1);
                }
            }
        }
        stg += STAGE_SZ;
        if (stg >= (uint32_t)NSTAGE*STAGE_SZ) stg = 0;
    }

    // ---- epilogue: y[tok] += g * acc ----
    int t4r = lane >> 2;
    int t4c = (lane & 3) * 2;
#pragma unroll
    for (int mi = 0; mi < 4; mi++) {
#pragma unroll
        for (int half = 0; half < 2; half++) {
            int r = wm + mi * 16 + half * 8 + t4r;
            int tok = tok_s[r];
            if (tok < 0) continue;
            float g = gat_s[r];
            float* yr = y + (size_t)tok * DOUT + n0;
#pragma unroll
            for (int nj = 0; nj < 4; nj++) {
                int cn = wn + nj * 8 + t4c;
                atomicAdd(yr + cn,     g * acc[mi][nj][half*2]);
                atomicAdd(yr + cn + 1, g * acc[mi][nj][half*2+1]);
            }
        }
    }
}

// ---------------- launch ----------------
extern "C" void kernel_launch(void* const* d_in, const int* in_sizes, int n_in,
                              void* d_out, int out_size) {
    const float* x        = (const float*)d_in[0];   // [2048, 768]
    const float* w_gate   = (const float*)d_in[1];   // [768, 8]
    const float* expert_w = (const float*)d_in[2];   // [8, 3072, 768]
    const float* expert_b = (const float*)d_in[3];   // [8, 3072]
    const float* static_w = (const float*)d_in[4];   // [3072, 768]
    float* out = (float*)d_out;

    cudaFuncSetAttribute(moe_gemm_mma, cudaFuncAttributeMaxDynamicSharedMemorySize, SMEM_SZ);

    zero_kernel<<<1, 32>>>();
    gate_kernel<<<NTOK/8, 256>>>(x, w_gate);
    loss_kernel<<<1, 1>>>(out, out_size);

    split_x_kernel<<<(NTOK*DIN/8 + 255)/256, 256>>>(x);
    split_cw_kernel<<<(NEXP*DOUT*DIN/8 + 255)/256, 256>>>(expert_w, static_w);

    dim3 igrid(DOUT/1024, NTOK);             // 3 x 2048
    init_y_kernel<<<igrid, 256>>>(out, expert_b);

    dim3 egrid(DOUT/BN, NTOK/BM, NEXP);      // 12 x 16 x 8 (early exit on cnt)
    moe_gemm_mma<<<egrid, 512, SMEM_SZ>>>(out);
}

// round 7
// speedup vs baseline: 5.0308x; 1.0194x over previous
#include <cuda_runtime.h>
#include <cuda_bf16.h>
#include <cuda_fp16.h>
#include <cstdint>

// ---------------- problem constants ----------------
#define NTOK 2048      // B*S
#define DIN  768       // D
#define NEXP 8         // E
#define DOUT 3072      // O
#define NO   (NTOK*DOUT)

// ---------------- GEMM tiling ----------------
#define BM 128
#define BN 256
#define BK 32                  // fp16 elems per chunk (64B per row)
#define NCH (DIN/BK)           // 24
#define RSTRIDE 80             // smem row stride bytes (conflict-free ldmatrix)
#define NSTAGE 3

// smem layout
#define OFF_TOK 0              // 128 int
#define OFF_GAT 512            // 128 float
#define OFF_ST0 1024
#define AOFFS 0
#define BOFFS (128*RSTRIDE)                 // 10240
#define STAGE_SZ (128*RSTRIDE + 256*RSTRIDE)   // 30720
#define SMEM_SZ (OFF_ST0 + NSTAGE*STAGE_SZ)    // 93184

// ---------------- device scratch ----------------
__device__ int   g_counts[NEXP];
__device__ float g_importance[NEXP];
__device__ int   g_list[NEXP * NTOK];
__device__ float g_gateval[NEXP * NTOK];
__device__ int   g_tokexp[NTOK * 2];
__device__ float g_tokgate[NTOK * 2];

__device__ __align__(256) __half g_xh[NTOK*DIN];
__device__ __align__(256) __half g_cwh[NEXP*DOUT*DIN];   // fp16(expert_w + static_w)

// ---------------- PTX helpers (baseline sm_80+, no 'a' features) ----------
__device__ __forceinline__ uint32_t smem_u32(const void* p) {
    uint32_t a;
    asm("{ .reg .u64 t; cvta.to.shared.u64 t, %1; cvt.u32.u64 %0, t; }"
        : "=r"(a) : "l"(p));
    return a;
}
__device__ __forceinline__ void cpasync16(uint32_t dst, const void* src) {
    asm volatile("cp.async.cg.shared.global [%0], [%1], 16;" :: "r"(dst), "l"(src));
}
#define CP_COMMIT() asm volatile("cp.async.commit_group;" ::: "memory")
#define CP_WAIT(n)  asm volatile("cp.async.wait_group %0;" :: "n"(n) : "memory")

__device__ __forceinline__ void ldsm4(uint32_t* r, uint32_t addr) {
    asm volatile("ldmatrix.sync.aligned.m8n8.x4.shared.b16 {%0,%1,%2,%3}, [%4];"
        : "=r"(r[0]), "=r"(r[1]), "=r"(r[2]), "=r"(r[3]) : "r"(addr));
}
__device__ __forceinline__ void mma16816(float* c, const uint32_t* a,
                                         uint32_t b0, uint32_t b1) {
    asm volatile("mma.sync.aligned.m16n8k16.row.col.f32.f16.f16.f32 "
        "{%0,%1,%2,%3}, {%4,%5,%6,%7}, {%8,%9}, {%0,%1,%2,%3};"
        : "+f"(c[0]), "+f"(c[1]), "+f"(c[2]), "+f"(c[3])
        : "r"(a[0]), "r"(a[1]), "r"(a[2]), "r"(a[3]), "r"(b0), "r"(b1));
}

// ---------------- kernel: zero counters ----------------
__global__ void zero_kernel() {
    int t = threadIdx.x;
    if (t < NEXP) { g_counts[t] = 0; g_importance[t] = 0.0f; }
}

// ---------------- kernel: gating (one WARP per token) ----------------
__global__ __launch_bounds__(256)
void gate_kernel(const float* __restrict__ x, const float* __restrict__ wg) {
    int gw   = (blockIdx.x * 256 + threadIdx.x) >> 5;   // global warp = token
    int lane = threadIdx.x & 31;
    if (gw >= NTOK) return;

    const float4* xr = (const float4*)(x + (size_t)gw * DIN);
    float acc[NEXP];
#pragma unroll
    for (int e = 0; e < NEXP; e++) acc[e] = 0.0f;

#pragma unroll
    for (int it = 0; it < DIN/4/32; it++) {             // 6 iters
        int i = it * 32 + lane;
        float4 v = xr[i];
        const float* w0 = wg + (size_t)(i * 4) * NEXP;
#pragma unroll
        for (int e = 0; e < NEXP; e++)
            acc[e] += v.x * w0[e] + v.y * w0[NEXP + e]
                    + v.z * w0[2*NEXP + e] + v.w * w0[3*NEXP + e];
    }
#pragma unroll
    for (int e = 0; e < NEXP; e++) {
#pragma unroll
        for (int off = 16; off > 0; off >>= 1)
            acc[e] += __shfl_xor_sync(0xffffffffu, acc[e], off);
    }
    if (lane == 0) {
        float best = acc[0], second = -3.4e38f;
        int bi = 0, si = -1;
#pragma unroll
        for (int e = 1; e < NEXP; e++) {
            if (acc[e] > best)        { second = best; si = bi; best = acc[e]; bi = e; }
            else if (acc[e] > second) { second = acc[e]; si = e; }
        }
        float e1 = __expf(second - best);
        float inv = 1.0f / (1.0f + e1);
        float g0 = inv, g1 = e1 * inv;
        atomicAdd(&g_importance[bi], g0);
        atomicAdd(&g_importance[si], g1);
        int p0 = atomicAdd(&g_counts[bi], 1);
        g_list[bi * NTOK + p0] = gw;  g_gateval[bi * NTOK + p0] = g0;
        int p1 = atomicAdd(&g_counts[si], 1);
        g_list[si * NTOK + p1] = gw;  g_gateval[si * NTOK + p1] = g1;
        g_tokexp[2*gw] = bi;  g_tokexp[2*gw+1] = si;
        g_tokgate[2*gw] = g0; g_tokgate[2*gw+1] = g1;
    }
}

// ---------------- kernel: loss ----------------
__global__ void loss_kernel(float* __restrict__ out, int out_size) {
    if (out_size <= NO) return;
    float mi = 0.0f, ml = 0.0f;
#pragma unroll
    for (int e = 0; e < NEXP; e++) { mi += g_importance[e]; ml += (float)g_counts[e]; }
    mi *= (1.0f / NEXP); ml *= (1.0f / NEXP);
    float vi = 0.0f, vl = 0.0f;
#pragma unroll
    for (int e = 0; e < NEXP; e++) {
        float di = g_importance[e] - mi;    vi += di * di;
        float dl = (float)g_counts[e] - ml; vl += dl * dl;
    }
    vi *= (1.0f / (NEXP - 1)); vl *= (1.0f / (NEXP - 1));
    out[NO] = 0.01f * (vi / (mi * mi + 1e-10f) + vl / (ml * ml + 1e-10f));
}

// ---------------- fp32x8 -> fp16x8 pack ----------------
__device__ __forceinline__ uint4 cvt8(const float4 a, const float4 b) {
    __half2 h0 = __floats2half2_rn(a.x, a.y);
    __half2 h1 = __floats2half2_rn(a.z, a.w);
    __half2 h2 = __floats2half2_rn(b.x, b.y);
    __half2 h3 = __floats2half2_rn(b.z, b.w);
    uint4 r;
    r.x = *(uint32_t*)&h0; r.y = *(uint32_t*)&h1;
    r.z = *(uint32_t*)&h2; r.w = *(uint32_t*)&h3;
    return r;
}

// ---------------- kernel: x -> fp16 (16 elems/thread) ----------------
__global__ __launch_bounds__(256)
void split_x_kernel(const float* __restrict__ s) {
    int i = blockIdx.x * 256 + threadIdx.x;       // 16 elems per thread
    if (i >= NTOK*DIN/16) return;
    float4 a0 = ((const float4*)s)[4*i];
    float4 b0 = ((const float4*)s)[4*i + 1];
    float4 a1 = ((const float4*)s)[4*i + 2];
    float4 b1 = ((const float4*)s)[4*i + 3];
    ((uint4*)g_xh)[2*i]     = cvt8(a0, b0);
    ((uint4*)g_xh)[2*i + 1] = cvt8(a1, b1);
}

// ---------------- kernel: fp16(expert_w + static_w), 16 elems/thread -------
// 8 independent LDG.128 in flight per thread (MLP=8) to escape latency bound.
__global__ __launch_bounds__(256)
void split_cw_kernel(const float* __restrict__ ew, const float* __restrict__ sw) {
    int i = blockIdx.x * 256 + threadIdx.x;       // group of 16 elems
    if (i >= NEXP*DOUT*DIN/16) return;
    int si = i % (DOUT*DIN/16);
    float4 e0 = ((const float4*)ew)[4*i];
    float4 e1 = ((const float4*)ew)[4*i + 1];
    float4 e2 = ((const float4*)ew)[4*i + 2];
    float4 e3 = ((const float4*)ew)[4*i + 3];
    float4 s0 = ((const float4*)sw)[4*si];
    float4 s1 = ((const float4*)sw)[4*si + 1];
    float4 s2 = ((const float4*)sw)[4*si + 2];
    float4 s3 = ((const float4*)sw)[4*si + 3];
    float4 a0 = { e0.x + s0.x, e0.y + s0.y, e0.z + s0.z, e0.w + s0.w };
    float4 b0 = { e1.x + s1.x, e1.y + s1.y, e1.z + s1.z, e1.w + s1.w };
    float4 a1 = { e2.x + s2.x, e2.y + s2.y, e2.z + s2.z, e2.w + s2.w };
    float4 b1 = { e3.x + s3.x, e3.y + s3.y, e3.z + s3.z, e3.w + s3.w };
    ((uint4*)g_cwh)[2*i]     = cvt8(a0, b0);
    ((uint4*)g_cwh)[2*i + 1] = cvt8(a1, b1);
}

// ---------------- kernel: init y with gated biases --------------------------
__global__ __launch_bounds__(256)
void init_y_kernel(float* __restrict__ y, const float* __restrict__ eb) {
    int n = blockIdx.y;
    int o = blockIdx.x * 1024 + threadIdx.x * 4;
    int e0 = g_tokexp[2*n], e1 = g_tokexp[2*n+1];
    float g0 = g_tokgate[2*n], g1 = g_tokgate[2*n+1];
    float4 b0 = *(const float4*)(eb + (size_t)e0 * DOUT + o);
    float4 b1 = *(const float4*)(eb + (size_t)e1 * DOUT + o);
    float4 r = { g0*b0.x + g1*b1.x, g0*b0.y + g1*b1.y,
                 g0*b0.z + g1*b1.z, g0*b0.w + g1*b1.w };
    *(float4*)(y + (size_t)n * DOUT + o) = r;
}

// ---------------- kernel: fp16 mma.sync expert GEMM ------------------------
// 256 threads, 8 warps, warp tile 64x64 (2m x 4n), 3-stage cp.async.
// Per ks: 8 ldsm.x4 per 32 HMMA (half the LDSM pressure of 64x32 tiles).
__global__ __launch_bounds__(256, 1)
void moe_gemm_mma(float* __restrict__ y) {
    extern __shared__ char sm[];
    uint32_t sb = smem_u32(sm);
    int tid = threadIdx.x, wid = tid >> 5, lane = tid & 31;
    int n0 = blockIdx.x * BN;
    int m0 = blockIdx.y * BM;
    int e  = blockIdx.z;
    int cnt = g_counts[e];
    if (m0 >= cnt) return;

    int* tok_s   = (int*)(sm + OFF_TOK);
    float* gat_s = (float*)(sm + OFF_GAT);
    if (tid < BM) {
        int idx = m0 + tid;
        if (idx < cnt) { tok_s[tid] = g_list[e*NTOK + idx]; gat_s[tid] = g_gateval[e*NTOK + idx]; }
        else           { tok_s[tid] = -1; gat_s[tid] = 0.0f; }
    }
    __syncthreads();

    // ---- cp.async geometry: 6 x 16B per thread per stage ----
    int c  = tid & 3;                 // 16B chunk in 64B row
    int rr = tid >> 2;                // 0..63
    size_t wbase = (size_t)e * DOUT * DIN;
    size_t srcA[2]; uint32_t dstA[2];
#pragma unroll
    for (int i = 0; i < 2; i++) {
        int r = rr + i * 64;
        int t = tok_s[r];
        srcA[i] = (size_t)((t < 0) ? 0 : t) * DIN + c * 8;
        dstA[i] = r * RSTRIDE + c * 16;
    }
    size_t srcB[4]; uint32_t dstB[4];
#pragma unroll
    for (int i = 0; i < 4; i++) {
        int r = rr + i * 64;
        srcB[i] = wbase + (size_t)(n0 + r) * DIN + c * 8;
        dstB[i] = r * RSTRIDE + c * 16;
    }

    auto load_chunk = [&](int ch, uint32_t stg) {
        int off = ch * BK;
        uint32_t s0 = sb + OFF_ST0 + stg;
#pragma unroll
        for (int i = 0; i < 2; i++)
            cpasync16(s0 + AOFFS + dstA[i], g_xh + srcA[i] + off);
#pragma unroll
        for (int i = 0; i < 4; i++)
            cpasync16(s0 + BOFFS + dstB[i], g_cwh + srcB[i] + off);
        CP_COMMIT();
    };

    // ---- ldmatrix per-lane base offsets (warp tile 64x64, 2x4 warps) ----
    int wm = (wid >> 2) * 64;         // 0 or 64
    int wn = (wid & 3) * 64;          // 0,64,128,192
    int mat = lane >> 3, r8 = lane & 7;
    uint32_t aoff = (uint32_t)((wm + (mat & 1) * 8 + r8) * RSTRIDE + (mat >> 1) * 16);
    uint32_t boff = (uint32_t)((wn + ((mat >> 1) & 1) * 8 + r8) * RSTRIDE + (mat & 1) * 16);

    float acc[4][8][4] = {};

    load_chunk(0, 0);
    load_chunk(1, STAGE_SZ);

    uint32_t stg = 0;
    for (int ch = 0; ch < NCH; ch++) {
        if (ch < NCH - 1) { CP_WAIT(1); } else { CP_WAIT(0); }
        __syncthreads();
        if (ch + 2 < NCH) {
            uint32_t nst = stg + 2*STAGE_SZ;
            if (nst >= (uint32_t)NSTAGE*STAGE_SZ) nst -= NSTAGE*STAGE_SZ;
            load_chunk(ch + 2, nst);
        }

        uint32_t aBase = sb + OFF_ST0 + stg + AOFFS + aoff;
        uint32_t bBase = sb + OFF_ST0 + stg + BOFFS + boff;

#pragma unroll
        for (int ks = 0; ks < 2; ks++) {
            uint32_t ah[4][4], bh[4][4];
#pragma unroll
            for (int mi = 0; mi < 4; mi++)
                ldsm4(ah[mi], aBase + mi * (16 * RSTRIDE) + ks * 32);
#pragma unroll
            for (int nt = 0; nt < 4; nt++)
                ldsm4(bh[nt], bBase + nt * (16 * RSTRIDE) + ks * 32);
#pragma unroll
            for (int mi = 0; mi < 4; mi++) {
#pragma unroll
                for (int nj = 0; nj < 8; nj++) {
                    uint32_t h0 = bh[nj >> 1][(nj & 1) * 2];
                    uint32_t h1 = bh[nj >> 1][(nj & 1) * 2 + 1];
                    mma16816(acc[mi][nj], ah[mi], h0, h1);
                }
            }
        }
        stg += STAGE_SZ;
        if (stg >= (uint32_t)NSTAGE*STAGE_SZ) stg = 0;
    }

    // ---- epilogue: y[tok] += g * acc ----
    int t4r = lane >> 2;
    int t4c = (lane & 3) * 2;
#pragma unroll
    for (int mi = 0; mi < 4; mi++) {
#pragma unroll
        for (int half = 0; half < 2; half++) {
            int r = wm + mi * 16 + half * 8 + t4r;
            int tok = tok_s[r];
            if (tok < 0) continue;
            float g = gat_s[r];
            float* yr = y + (size_t)tok * DOUT + n0;
#pragma unroll
            for (int nj = 0; nj < 8; nj++) {
                int cn = wn + nj * 8 + t4c;
                atomicAdd(yr + cn,     g * acc[mi][nj][half*2]);
                atomicAdd(yr + cn + 1, g * acc[mi][nj][half*2+1]);
            }
        }
    }
}

// ---------------- launch ----------------
extern "C" void kernel_launch(void* const* d_in, const int* in_sizes, int n_in,
                              void* d_out, int out_size) {
    const float* x        = (const float*)d_in[0];   // [2048, 768]
    const float* w_gate   = (const float*)d_in[1];   // [768, 8]
    const float* expert_w = (const float*)d_in[2];   // [8, 3072, 768]
    const float* expert_b = (const float*)d_in[3];   // [8, 3072]
    const float* static_w = (const float*)d_in[4];   // [3072, 768]
    float* out = (float*)d_out;

    cudaFuncSetAttribute(moe_gemm_mma, cudaFuncAttributeMaxDynamicSharedMemorySize, SMEM_SZ);

    zero_kernel<<<1, 32>>>();
    gate_kernel<<<NTOK/8, 256>>>(x, w_gate);
    loss_kernel<<<1, 1>>>(out, out_size);

    split_x_kernel<<<(NTOK*DIN/16 + 255)/256, 256>>>(x);
    split_cw_kernel<<<(NEXP*DOUT*DIN/16 + 255)/256, 256>>>(expert_w, static_w);

    dim3 igrid(DOUT/1024, NTOK);             // 3 x 2048
    init_y_kernel<<<igrid, 256>>>(out, expert_b);

    dim3 egrid(DOUT/BN, NTOK/BM, NEXP);      // 12 x 16 x 8 (early exit on cnt)
    moe_gemm_mma<<<egrid, 256, SMEM_SZ>>>(out);
}